// round 3
// baseline (speedup 1.0000x reference)
#include <cuda_runtime.h>
#include <cstdint>

#define T_LEN   1000000
#define HIDDEN  75
#define NS      16

// Scratch (no allocations allowed): negated log-softmax priors and per-step metrics.
__device__ float g_cneg[T_LEN * NS];   // c[t][i] = -log_softmax(logits_t)[i]  (64 MB)
__device__ float g_q[T_LEN * 8];       // 8 distinct path metrics per step, pre-update (32 MB)

// ---------------------------------------------------------------------------
// K1: priors. Mirrors the jax fp32 pipeline:
//   h  = relu( fl( fl(rx*W1_j) + b1_j ) )          (separate mul/add roundings)
//   l  = dot(h, W2[:,k]) (fp32 fma) + b2_k
//   prior = (l - max) - log(sum(exp(l - max)))
// stores cneg = -prior.
// ---------------------------------------------------------------------------
__global__ __launch_bounds__(256)
void priors_kernel(const float* __restrict__ rx,
                   const float* __restrict__ W1,
                   const float* __restrict__ b1,
                   const float* __restrict__ W2,
                   const float* __restrict__ b2)
{
    __shared__ float  sW1[HIDDEN];
    __shared__ float  sb1[HIDDEN];
    __shared__ float  sb2[NS];
    __shared__ float4 sW2[HIDDEN * 4];   // [75][16] row-major as float4 x4

    int tid = threadIdx.x;
    for (int i = tid; i < HIDDEN; i += blockDim.x) { sW1[i] = W1[i]; sb1[i] = b1[i]; }
    for (int i = tid; i < HIDDEN * 4; i += blockDim.x)
        sW2[i] = reinterpret_cast<const float4*>(W2)[i];
    if (tid < NS) sb2[tid] = b2[tid];
    __syncthreads();

    int t = blockIdx.x * blockDim.x + tid;
    if (t >= T_LEN) return;

    float r = rx[t];

    float acc[NS];
#pragma unroll
    for (int k = 0; k < NS; k++) acc[k] = 0.0f;

#pragma unroll 5
    for (int j = 0; j < HIDDEN; j++) {
        float h = __fadd_rn(__fmul_rn(r, sW1[j]), sb1[j]);
        h = fmaxf(h, 0.0f);
        float4 w0 = sW2[j * 4 + 0];
        float4 w1 = sW2[j * 4 + 1];
        float4 w2 = sW2[j * 4 + 2];
        float4 w3 = sW2[j * 4 + 3];
        acc[0]  = __fmaf_rn(h, w0.x, acc[0]);
        acc[1]  = __fmaf_rn(h, w0.y, acc[1]);
        acc[2]  = __fmaf_rn(h, w0.z, acc[2]);
        acc[3]  = __fmaf_rn(h, w0.w, acc[3]);
        acc[4]  = __fmaf_rn(h, w1.x, acc[4]);
        acc[5]  = __fmaf_rn(h, w1.y, acc[5]);
        acc[6]  = __fmaf_rn(h, w1.z, acc[6]);
        acc[7]  = __fmaf_rn(h, w1.w, acc[7]);
        acc[8]  = __fmaf_rn(h, w2.x, acc[8]);
        acc[9]  = __fmaf_rn(h, w2.y, acc[9]);
        acc[10] = __fmaf_rn(h, w2.z, acc[10]);
        acc[11] = __fmaf_rn(h, w2.w, acc[11]);
        acc[12] = __fmaf_rn(h, w3.x, acc[12]);
        acc[13] = __fmaf_rn(h, w3.y, acc[13]);
        acc[14] = __fmaf_rn(h, w3.z, acc[14]);
        acc[15] = __fmaf_rn(h, w3.w, acc[15]);
    }

    float logit[NS];
#pragma unroll
    for (int k = 0; k < NS; k++) logit[k] = __fadd_rn(acc[k], sb2[k]);

    float m = logit[0];
#pragma unroll
    for (int k = 1; k < NS; k++) m = fmaxf(m, logit[k]);

    float sh[NS];
    float s = 0.0f;
#pragma unroll
    for (int k = 0; k < NS; k++) {
        sh[k] = __fadd_rn(logit[k], -m);
        s = __fadd_rn(s, expf(sh[k]));
    }
    float lse = logf(s);

    float out[NS];
#pragma unroll
    for (int k = 0; k < NS; k++)
        out[k] = -__fadd_rn(sh[k], -lse);   // cneg = -(shifted - lse)

    float4* dst = reinterpret_cast<float4*>(&g_cneg[(size_t)t * NS]);
    dst[0] = make_float4(out[0],  out[1],  out[2],  out[3]);
    dst[1] = make_float4(out[4],  out[5],  out[6],  out[7]);
    dst[2] = make_float4(out[8],  out[9],  out[10], out[11]);
    dst[3] = make_float4(out[12], out[13], out[14], out[15]);
}

// ---------------------------------------------------------------------------
// K2: the serial ACS recurrence (single thread — the chain is irreducible).
// p'[s] = min( fl(p[2s%16] + c[2s]), fl(p[(2s+1)%16] + c[2s+1]) ), p[i]=q[i&7].
// Stores the pre-update metrics each step; argmin/softmax are done off-chain in K3.
// ---------------------------------------------------------------------------
__global__ void viterbi_kernel()
{
    if (threadIdx.x != 0 || blockIdx.x != 0) return;

    float q0 = 0.f, q1 = 0.f, q2 = 0.f, q3 = 0.f;
    float q4 = 0.f, q5 = 0.f, q6 = 0.f, q7 = 0.f;

    const float4* __restrict__ cn = reinterpret_cast<const float4*>(g_cneg);
    float4* __restrict__ qs = reinterpret_cast<float4*>(g_q);

#pragma unroll 4
    for (int t = 0; t < T_LEN; t++) {
        // record metrics BEFORE the update (outputs use the incoming metrics)
        qs[2 * t + 0] = make_float4(q0, q1, q2, q3);
        qs[2 * t + 1] = make_float4(q4, q5, q6, q7);

        const float4 c0 = __ldg(&cn[4 * t + 0]);
        const float4 c1 = __ldg(&cn[4 * t + 1]);
        const float4 c2 = __ldg(&cn[4 * t + 2]);
        const float4 c3 = __ldg(&cn[4 * t + 3]);

        float x0  = __fadd_rn(q0, c0.x);
        float x1  = __fadd_rn(q1, c0.y);
        float x2  = __fadd_rn(q2, c0.z);
        float x3  = __fadd_rn(q3, c0.w);
        float x4  = __fadd_rn(q4, c1.x);
        float x5  = __fadd_rn(q5, c1.y);
        float x6  = __fadd_rn(q6, c1.z);
        float x7  = __fadd_rn(q7, c1.w);
        float x8  = __fadd_rn(q0, c2.x);
        float x9  = __fadd_rn(q1, c2.y);
        float x10 = __fadd_rn(q2, c2.z);
        float x11 = __fadd_rn(q3, c2.w);
        float x12 = __fadd_rn(q4, c3.x);
        float x13 = __fadd_rn(q5, c3.y);
        float x14 = __fadd_rn(q6, c3.z);
        float x15 = __fadd_rn(q7, c3.w);

        q0 = fminf(x0,  x1);
        q1 = fminf(x2,  x3);
        q2 = fminf(x4,  x5);
        q3 = fminf(x6,  x7);
        q4 = fminf(x8,  x9);
        q5 = fminf(x10, x11);
        q6 = fminf(x12, x13);
        q7 = fminf(x14, x15);
    }
}

// ---------------------------------------------------------------------------
// K3: per-step outputs from stored metrics (fully parallel).
// det  = (first argmin over 16 duplicated metrics) % 2 == (first argmin over q[0..7]) & 1
// 2*conf = 2 * 1/sum16 = 1/sum8, sum8 = sum_s exp(-(q_s - min))
// ---------------------------------------------------------------------------
__global__ __launch_bounds__(256)
void output_kernel(float* __restrict__ out)
{
    int t = blockIdx.x * blockDim.x + threadIdx.x;
    if (t >= T_LEN) return;

    const float4* qs = reinterpret_cast<const float4*>(g_q);
    float4 a = qs[2 * t + 0];
    float4 b = qs[2 * t + 1];
    float q[8] = { a.x, a.y, a.z, a.w, b.x, b.y, b.z, b.w };

    float m = q[0];
    int idx = 0;
#pragma unroll
    for (int s = 1; s < 8; s++) {
        if (q[s] < m) { m = q[s]; idx = s; }   // strict <  => first-index argmin
    }

    float sum = 0.0f;
#pragma unroll
    for (int s = 0; s < 8; s++)
        sum += expf(-(q[s] - m));

    out[t]          = (float)(idx & 1);   // detected_word
    out[T_LEN + t]  = 1.0f / sum;         // 2 * confidence_word
}

// ---------------------------------------------------------------------------
// Launch. Inputs per metadata order: rx[1e6], W1[75], b1[75], W2[1200], b2[16].
// Output: 2*T floats, det first then 2*conf.
// ---------------------------------------------------------------------------
extern "C" void kernel_launch(void* const* d_in, const int* in_sizes, int n_in,
                              void* d_out, int out_size)
{
    const float* rx = (const float*)d_in[0];
    const float* W1 = (const float*)d_in[1];
    const float* b1 = (const float*)d_in[2];
    const float* W2 = (const float*)d_in[3];
    const float* b2 = (const float*)d_in[4];
    float* out = (float*)d_out;

    int blocks = (T_LEN + 255) / 256;
    priors_kernel<<<blocks, 256>>>(rx, W1, b1, W2, b2);
    viterbi_kernel<<<1, 32>>>();
    output_kernel<<<blocks, 256>>>(out);
}

// round 6
// speedup vs baseline: 5.9064x; 5.9064x over previous
#include <cuda_runtime.h>
#include <cstdint>

#define T_LEN   1000000
#define HIDDEN  75
#define NS      16

#define CH      256                       // steps per pipeline chunk
#define NBUF    4                         // ring depth (power of 2)
#define NCHUNK  ((T_LEN + CH - 1) / CH)   // 3907 (last chunk = 64 steps)

// Shared layout: c ring | q ring | flags
#define C_RING_BYTES (NBUF * CH * 64)     // 16 floats/step
#define Q_RING_BYTES (NBUF * CH * 32)     // 8 floats/step
#define SMEM_BYTES   (C_RING_BYTES + Q_RING_BYTES + 64)

typedef unsigned long long ull;

// Scratch (no allocations allowed): negated log-softmax priors.
__device__ float g_cneg[T_LEN * NS];   // c[t][i] = -log_softmax(logits_t)[i]  (64 MB)

// ---------------------------------------------------------------------------
// packed f32x2 helpers (Blackwell): two independent IEEE fp32 RN adds per instr
// ---------------------------------------------------------------------------
__device__ __forceinline__ ull addx2(ull a, ull b) {
    ull r; asm("add.rn.f32x2 %0,%1,%2;" : "=l"(r) : "l"(a), "l"(b)); return r;
}
__device__ __forceinline__ ull packf2(float lo, float hi) {
    ull r; asm("mov.b64 %0,{%1,%2};" : "=l"(r) : "f"(lo), "f"(hi)); return r;
}
__device__ __forceinline__ float lof(ull v) { return __uint_as_float((unsigned)v); }
__device__ __forceinline__ float hif(ull v) { return __uint_as_float((unsigned)(v >> 32)); }

// ---------------------------------------------------------------------------
// K1: priors. Mirrors the jax fp32 pipeline (unchanged from passing round):
//   h  = relu( fl( fl(rx*W1_j) + b1_j ) )
//   l  = dot(h, W2[:,k]) (fp32 fma) + b2_k
//   prior = (l - max) - log(sum(exp(l - max)));  stores cneg = -prior.
// ---------------------------------------------------------------------------
__global__ __launch_bounds__(256)
void priors_kernel(const float* __restrict__ rx,
                   const float* __restrict__ W1,
                   const float* __restrict__ b1,
                   const float* __restrict__ W2,
                   const float* __restrict__ b2)
{
    __shared__ float  sW1[HIDDEN];
    __shared__ float  sb1[HIDDEN];
    __shared__ float  sb2[NS];
    __shared__ float4 sW2[HIDDEN * 4];

    int tid = threadIdx.x;
    for (int i = tid; i < HIDDEN; i += blockDim.x) { sW1[i] = W1[i]; sb1[i] = b1[i]; }
    for (int i = tid; i < HIDDEN * 4; i += blockDim.x)
        sW2[i] = reinterpret_cast<const float4*>(W2)[i];
    if (tid < NS) sb2[tid] = b2[tid];
    __syncthreads();

    int t = blockIdx.x * blockDim.x + tid;
    if (t >= T_LEN) return;

    float r = rx[t];

    float acc[NS];
#pragma unroll
    for (int k = 0; k < NS; k++) acc[k] = 0.0f;

#pragma unroll 5
    for (int j = 0; j < HIDDEN; j++) {
        float h = __fadd_rn(__fmul_rn(r, sW1[j]), sb1[j]);
        h = fmaxf(h, 0.0f);
        float4 w0 = sW2[j * 4 + 0];
        float4 w1 = sW2[j * 4 + 1];
        float4 w2 = sW2[j * 4 + 2];
        float4 w3 = sW2[j * 4 + 3];
        acc[0]  = __fmaf_rn(h, w0.x, acc[0]);
        acc[1]  = __fmaf_rn(h, w0.y, acc[1]);
        acc[2]  = __fmaf_rn(h, w0.z, acc[2]);
        acc[3]  = __fmaf_rn(h, w0.w, acc[3]);
        acc[4]  = __fmaf_rn(h, w1.x, acc[4]);
        acc[5]  = __fmaf_rn(h, w1.y, acc[5]);
        acc[6]  = __fmaf_rn(h, w1.z, acc[6]);
        acc[7]  = __fmaf_rn(h, w1.w, acc[7]);
        acc[8]  = __fmaf_rn(h, w2.x, acc[8]);
        acc[9]  = __fmaf_rn(h, w2.y, acc[9]);
        acc[10] = __fmaf_rn(h, w2.z, acc[10]);
        acc[11] = __fmaf_rn(h, w2.w, acc[11]);
        acc[12] = __fmaf_rn(h, w3.x, acc[12]);
        acc[13] = __fmaf_rn(h, w3.y, acc[13]);
        acc[14] = __fmaf_rn(h, w3.z, acc[14]);
        acc[15] = __fmaf_rn(h, w3.w, acc[15]);
    }

    float logit[NS];
#pragma unroll
    for (int k = 0; k < NS; k++) logit[k] = __fadd_rn(acc[k], sb2[k]);

    float m = logit[0];
#pragma unroll
    for (int k = 1; k < NS; k++) m = fmaxf(m, logit[k]);

    float sh[NS];
    float s = 0.0f;
#pragma unroll
    for (int k = 0; k < NS; k++) {
        sh[k] = __fadd_rn(logit[k], -m);
        s = __fadd_rn(s, expf(sh[k]));
    }
    float lse = logf(s);

    float out[NS];
#pragma unroll
    for (int k = 0; k < NS; k++)
        out[k] = -__fadd_rn(sh[k], -lse);

    float4* dst = reinterpret_cast<float4*>(&g_cneg[(size_t)t * NS]);
    dst[0] = make_float4(out[0],  out[1],  out[2],  out[3]);
    dst[1] = make_float4(out[4],  out[5],  out[6],  out[7]);
    dst[2] = make_float4(out[8],  out[9],  out[10], out[11]);
    dst[3] = make_float4(out[12], out[13], out[14], out[15]);
}

// ---------------------------------------------------------------------------
// K2: warp-specialized single-block pipeline.
//   tid 0        : serial ACS recurrence (exact reference fp32 op order)
//   tid 1..31    : idle (exit)
//   tid 32..95   : producers, gmem -> c ring     (bar.sync 1, 64)
//   tid 96..223  : drainers,  q ring -> det/conf (bar.sync 2, 128)
// ---------------------------------------------------------------------------
__global__ __launch_bounds__(224, 1)
void pipeline_kernel(float* __restrict__ out)
{
    extern __shared__ unsigned char dynsmem[];
    ull* c_ring = reinterpret_cast<ull*>(dynsmem);
    ull* q_ring = reinterpret_cast<ull*>(dynsmem + C_RING_BYTES);
    volatile int* flags = reinterpret_cast<volatile int*>(dynsmem + C_RING_BYTES + Q_RING_BYTES);
    volatile int* c_fill = flags;             // producer -> consumer
    volatile int* c_done = flags + NBUF;      // consumer -> producer
    volatile int* q_fill = flags + 2 * NBUF;  // consumer -> drainer
    volatile int* q_done = flags + 3 * NBUF;  // drainer -> consumer

    int tid = threadIdx.x;
    if (tid < 4 * NBUF) flags[tid] = 0;
    __syncthreads();

    if (tid == 0) {
        // ------------------- consumer: the serial chain -------------------
        ull P01 = 0, P23 = 0, P45 = 0, P67 = 0;   // packed (q0,q1)(q2,q3)(q4,q5)(q6,q7)
        for (int k = 0; k < NCHUNK; k++) {
            int b = k & (NBUF - 1);
            int e = k >> 2;                        // epoch (NBUF == 4)
            while (c_fill[b] < e + 1) {}
            while (q_done[b] < e) {}
            __threadfence_block();

            const longlong2* cb = reinterpret_cast<const longlong2*>(c_ring + (size_t)b * CH * 8);
            longlong2* qb = reinterpret_cast<longlong2*>(q_ring + (size_t)b * CH * 4);
            int n = (k == NCHUNK - 1) ? (T_LEN - k * CH) : CH;

#pragma unroll 8
            for (int s = 0; s < n; s++) {
                // record PRE-update metrics (outputs use incoming metrics)
                qb[2 * s + 0] = make_longlong2((long long)P01, (long long)P23);
                qb[2 * s + 1] = make_longlong2((long long)P45, (long long)P67);

                longlong2 v0 = cb[4 * s + 0];   // (c0,c1),(c2,c3)
                longlong2 v1 = cb[4 * s + 1];   // (c4,c5),(c6,c7)
                longlong2 v2 = cb[4 * s + 2];   // (c8,c9),(c10,c11)
                longlong2 v3 = cb[4 * s + 3];   // (c12,c13),(c14,c15)

                ull x01 = addx2(P01, (ull)v0.x);
                ull x23 = addx2(P23, (ull)v0.y);
                ull x45 = addx2(P45, (ull)v1.x);
                ull x67 = addx2(P67, (ull)v1.y);
                ull x89 = addx2(P01, (ull)v2.x);
                ull xab = addx2(P23, (ull)v2.y);
                ull xcd = addx2(P45, (ull)v3.x);
                ull xef = addx2(P67, (ull)v3.y);

                float q0 = fminf(lof(x01), hif(x01));
                float q1 = fminf(lof(x23), hif(x23));
                float q2 = fminf(lof(x45), hif(x45));
                float q3 = fminf(lof(x67), hif(x67));
                float q4 = fminf(lof(x89), hif(x89));
                float q5 = fminf(lof(xab), hif(xab));
                float q6 = fminf(lof(xcd), hif(xcd));
                float q7 = fminf(lof(xef), hif(xef));

                P01 = packf2(q0, q1);
                P23 = packf2(q2, q3);
                P45 = packf2(q4, q5);
                P67 = packf2(q6, q7);
            }
            __threadfence_block();
            q_fill[b] = e + 1;
            c_done[b] = e + 1;
        }
    } else if (tid < 32) {
        // idle lanes of warp 0 — exit (participate in NO named barriers)
        return;
    } else if (tid < 96) {
        // ------------------- producers: gmem -> c ring -------------------
        int p = tid - 32;   // 0..63
        const float4* src = reinterpret_cast<const float4*>(g_cneg);
        const long total4 = (long)T_LEN * 4;
        for (int k = 0; k < NCHUNK; k++) {
            int b = k & (NBUF - 1);
            int e = k >> 2;
            if (p == 0) { while (c_done[b] < e) {} }
            asm volatile("bar.sync 1, 64;" ::: "memory");
            float4* dst = reinterpret_cast<float4*>(c_ring + (size_t)b * CH * 8);
            long base4 = (long)k * (CH * 4);
#pragma unroll
            for (int j = 0; j < 16; j++) {
                int i = p + j * 64;                       // CH*4 = 1024 float4 per chunk
                if (base4 + i < total4) dst[i] = src[base4 + i];
            }
            asm volatile("bar.sync 1, 64;" ::: "memory");   // also drains STS
            if (p == 0) c_fill[b] = e + 1;
        }
    } else {
        // ------------------- drainers: q ring -> det/conf -> out ----------
        int d = tid - 96;  // 0..127
        for (int k = 0; k < NCHUNK; k++) {
            int b = k & (NBUF - 1);
            int e = k >> 2;
            if (d == 0) { while (q_fill[b] < e + 1) {} }
            asm volatile("bar.sync 2, 128;" ::: "memory");
            __threadfence_block();
            const ull* qb = q_ring + (size_t)b * CH * 4;
            int n = (k == NCHUNK - 1) ? (T_LEN - k * CH) : CH;
            for (int s = d; s < n; s += 128) {
                ull u0 = qb[4 * s + 0];
                ull u1 = qb[4 * s + 1];
                ull u2 = qb[4 * s + 2];
                ull u3 = qb[4 * s + 3];
                float q[8] = { lof(u0), hif(u0), lof(u1), hif(u1),
                               lof(u2), hif(u2), lof(u3), hif(u3) };
                float m = q[0];
                int idx = 0;
#pragma unroll
                for (int s2 = 1; s2 < 8; s2++)
                    if (q[s2] < m) { m = q[s2]; idx = s2; }  // first-index argmin
                float sum = 0.0f;
#pragma unroll
                for (int s2 = 0; s2 < 8; s2++)
                    sum += expf(-(q[s2] - m));
                int t = k * CH + s;
                out[t]         = (float)(idx & 1);   // detected_word
                out[T_LEN + t] = 1.0f / sum;         // 2 * confidence_word (== 2/sum16)
            }
            asm volatile("bar.sync 2, 128;" ::: "memory");
            if (d == 0) q_done[b] = e + 1;
        }
    }
}

// ---------------------------------------------------------------------------
// Launch. Inputs: rx[1e6], W1[75], b1[75], W2[1200], b2[16].
// Output: 2*T floats, det first then 2*conf.
// ---------------------------------------------------------------------------
extern "C" void kernel_launch(void* const* d_in, const int* in_sizes, int n_in,
                              void* d_out, int out_size)
{
    const float* rx = (const float*)d_in[0];
    const float* W1 = (const float*)d_in[1];
    const float* b1 = (const float*)d_in[2];
    const float* W2 = (const float*)d_in[3];
    const float* b2 = (const float*)d_in[4];
    float* out = (float*)d_out;

    cudaFuncSetAttribute(pipeline_kernel,
                         cudaFuncAttributeMaxDynamicSharedMemorySize, SMEM_BYTES);

    int blocks = (T_LEN + 255) / 256;
    priors_kernel<<<blocks, 256>>>(rx, W1, b1, W2, b2);
    pipeline_kernel<<<1, 224, SMEM_BYTES>>>(out);
}

// round 7
// speedup vs baseline: 8.5144x; 1.4416x over previous
#include <cuda_runtime.h>
#include <cstdint>

#define T_LEN   1000000
#define HIDDEN  75
#define NS      16

#define CH      256                       // steps per pipeline chunk
#define NBUF    4                         // ring depth (power of 2)
#define NCHUNK  ((T_LEN + CH - 1) / CH)   // 3907 (last chunk = 64 steps, even)

// Shared layout: c ring | q ring | flags
#define C_RING_BYTES (NBUF * CH * 64)     // 16 floats/step
#define Q_RING_BYTES (NBUF * CH * 32)     // 8 floats/step
#define SMEM_BYTES   (C_RING_BYTES + Q_RING_BYTES + 256)

typedef unsigned long long ull;

// Scratch (no allocations allowed): negated log-softmax priors.
__device__ float g_cneg[T_LEN * NS];   // c[t][i] = -log_softmax(logits_t)[i]  (64 MB)

// ---------------------------------------------------------------------------
// helpers
// ---------------------------------------------------------------------------
__device__ __forceinline__ unsigned smem_u32(const void* p) {
    return (unsigned)__cvta_generic_to_shared(p);
}
// two independent IEEE fp32 RN adds per instr (Blackwell packed f32x2)
__device__ __forceinline__ ull addx2(ull a, ull b) {
    ull r; asm("add.rn.f32x2 %0,%1,%2;" : "=l"(r) : "l"(a), "l"(b)); return r;
}
// (min(a.lo,a.hi), min(b.lo,b.hi)) — fused so ptxas can allocate halves in place
__device__ __forceinline__ ull minpair(ull a, ull b) {
    ull r;
    asm("{\n\t.reg .f32 al,ah,bl,bh,rl,rh;\n\t"
        "mov.b64 {al,ah},%1;\n\t"
        "mov.b64 {bl,bh},%2;\n\t"
        "min.f32 rl,al,ah;\n\t"
        "min.f32 rh,bl,bh;\n\t"
        "mov.b64 %0,{rl,rh};\n\t}"
        : "=l"(r) : "l"(a), "l"(b));
    return r;
}
__device__ __forceinline__ void lds128(ull& a, ull& b, unsigned addr) {
    asm volatile("ld.shared.v2.u64 {%0,%1},[%2];" : "=l"(a), "=l"(b) : "r"(addr));
}
__device__ __forceinline__ void sts64(unsigned addr, ull v) {
    asm volatile("st.shared.u64 [%0],%1;" :: "r"(addr), "l"(v));
}
__device__ __forceinline__ float lof(ull v) { return __uint_as_float((unsigned)v); }
__device__ __forceinline__ float hif(ull v) { return __uint_as_float((unsigned)(v >> 32)); }

// ---------------------------------------------------------------------------
// K1: priors. Mirrors the jax fp32 pipeline (unchanged from passing rounds).
// ---------------------------------------------------------------------------
__global__ __launch_bounds__(256)
void priors_kernel(const float* __restrict__ rx,
                   const float* __restrict__ W1,
                   const float* __restrict__ b1,
                   const float* __restrict__ W2,
                   const float* __restrict__ b2)
{
    __shared__ float  sW1[HIDDEN];
    __shared__ float  sb1[HIDDEN];
    __shared__ float  sb2[NS];
    __shared__ float4 sW2[HIDDEN * 4];

    int tid = threadIdx.x;
    for (int i = tid; i < HIDDEN; i += blockDim.x) { sW1[i] = W1[i]; sb1[i] = b1[i]; }
    for (int i = tid; i < HIDDEN * 4; i += blockDim.x)
        sW2[i] = reinterpret_cast<const float4*>(W2)[i];
    if (tid < NS) sb2[tid] = b2[tid];
    __syncthreads();

    int t = blockIdx.x * blockDim.x + tid;
    if (t >= T_LEN) return;

    float r = rx[t];

    float acc[NS];
#pragma unroll
    for (int k = 0; k < NS; k++) acc[k] = 0.0f;

#pragma unroll 5
    for (int j = 0; j < HIDDEN; j++) {
        float h = __fadd_rn(__fmul_rn(r, sW1[j]), sb1[j]);
        h = fmaxf(h, 0.0f);
        float4 w0 = sW2[j * 4 + 0];
        float4 w1 = sW2[j * 4 + 1];
        float4 w2 = sW2[j * 4 + 2];
        float4 w3 = sW2[j * 4 + 3];
        acc[0]  = __fmaf_rn(h, w0.x, acc[0]);
        acc[1]  = __fmaf_rn(h, w0.y, acc[1]);
        acc[2]  = __fmaf_rn(h, w0.z, acc[2]);
        acc[3]  = __fmaf_rn(h, w0.w, acc[3]);
        acc[4]  = __fmaf_rn(h, w1.x, acc[4]);
        acc[5]  = __fmaf_rn(h, w1.y, acc[5]);
        acc[6]  = __fmaf_rn(h, w1.z, acc[6]);
        acc[7]  = __fmaf_rn(h, w1.w, acc[7]);
        acc[8]  = __fmaf_rn(h, w2.x, acc[8]);
        acc[9]  = __fmaf_rn(h, w2.y, acc[9]);
        acc[10] = __fmaf_rn(h, w2.z, acc[10]);
        acc[11] = __fmaf_rn(h, w2.w, acc[11]);
        acc[12] = __fmaf_rn(h, w3.x, acc[12]);
        acc[13] = __fmaf_rn(h, w3.y, acc[13]);
        acc[14] = __fmaf_rn(h, w3.z, acc[14]);
        acc[15] = __fmaf_rn(h, w3.w, acc[15]);
    }

    float logit[NS];
#pragma unroll
    for (int k = 0; k < NS; k++) logit[k] = __fadd_rn(acc[k], sb2[k]);

    float m = logit[0];
#pragma unroll
    for (int k = 1; k < NS; k++) m = fmaxf(m, logit[k]);

    float sh[NS];
    float s = 0.0f;
#pragma unroll
    for (int k = 0; k < NS; k++) {
        sh[k] = __fadd_rn(logit[k], -m);
        s = __fadd_rn(s, expf(sh[k]));
    }
    float lse = logf(s);

    float out[NS];
#pragma unroll
    for (int k = 0; k < NS; k++)
        out[k] = -__fadd_rn(sh[k], -lse);

    float4* dst = reinterpret_cast<float4*>(&g_cneg[(size_t)t * NS]);
    dst[0] = make_float4(out[0],  out[1],  out[2],  out[3]);
    dst[1] = make_float4(out[4],  out[5],  out[6],  out[7]);
    dst[2] = make_float4(out[8],  out[9],  out[10], out[11]);
    dst[3] = make_float4(out[12], out[13], out[14], out[15]);
}

// one ACS step: state pairs M0=(q0,q1) M1=(q2,q3) M2=(q4,q5) M3=(q6,q7),
// c pairs C0..C7 in natural order. Exact reference fp32 op order.
#define ACS_STEP(C0,C1,C2,C3,C4,C5,C6,C7)                                   \
    do {                                                                    \
        ull y0 = addx2(M0, C0);                                             \
        ull y1 = addx2(M1, C1);                                             \
        ull y2 = addx2(M2, C2);                                             \
        ull y3 = addx2(M3, C3);                                             \
        ull y4 = addx2(M0, C4);                                             \
        ull y5 = addx2(M1, C5);                                             \
        ull y6 = addx2(M2, C6);                                             \
        ull y7 = addx2(M3, C7);                                             \
        M0 = minpair(y0, y1);                                               \
        M1 = minpair(y2, y3);                                               \
        M2 = minpair(y4, y5);                                               \
        M3 = minpair(y6, y7);                                               \
    } while (0)

// ---------------------------------------------------------------------------
// K2: warp-specialized single-block pipeline.
//   tid 0        : serial ACS recurrence (software-pipelined LDS, f32x2 math)
//   tid 1..31    : exit
//   tid 32..95   : producers, gmem -> c ring     (bar.sync 1, 64)
//   tid 96..223  : drainers,  q ring -> det/conf (bar.sync 2, 128)
// ---------------------------------------------------------------------------
__global__ __launch_bounds__(224, 1)
void pipeline_kernel(float* __restrict__ out)
{
    extern __shared__ unsigned char dynsmem[];
    ull* c_ring = reinterpret_cast<ull*>(dynsmem);
    ull* q_ring = reinterpret_cast<ull*>(dynsmem + C_RING_BYTES);
    volatile int* flags = reinterpret_cast<volatile int*>(dynsmem + C_RING_BYTES + Q_RING_BYTES);
    volatile int* c_fill = flags;             // producer -> consumer
    volatile int* c_done = flags + NBUF;      // consumer -> producer
    volatile int* q_fill = flags + 2 * NBUF;  // consumer -> drainer
    volatile int* q_done = flags + 3 * NBUF;  // drainer -> consumer

    int tid = threadIdx.x;
    if (tid < 4 * NBUF) flags[tid] = 0;
    __syncthreads();

    if (tid == 0) {
        // ------------------- consumer: the serial chain -------------------
        const unsigned c_base0 = smem_u32(c_ring);
        const unsigned q_base0 = smem_u32(q_ring);
        ull M0 = 0, M1 = 0, M2 = 0, M3 = 0;   // (q0,q1)(q2,q3)(q4,q5)(q6,q7)

        for (int k = 0; k < NCHUNK; k++) {
            int b = k & (NBUF - 1);
            int e = k >> 2;                    // epoch (NBUF == 4)
            while (c_fill[b] < e + 1) {}
            while (q_done[b] < e) {}
            __threadfence_block();

            const unsigned cbase = c_base0 + (unsigned)b * (CH * 64);
            const unsigned qbase = q_base0 + (unsigned)b * (CH * 32);
            const int n = (k == NCHUNK - 1) ? (T_LEN - k * CH) : CH;   // even

            ull A0,A1,A2,A3,A4,A5,A6,A7;
            ull B0,B1,B2,B3,B4,B5,B6,B7;
            // preload step 0
            lds128(A0, A1, cbase +  0);
            lds128(A2, A3, cbase + 16);
            lds128(A4, A5, cbase + 32);
            lds128(A6, A7, cbase + 48);

            for (int s = 0; s < n; s += 2) {
                unsigned ca = cbase + (unsigned)s * 64;
                unsigned qa = qbase + (unsigned)s * 32;

                // prefetch step s+1
                lds128(B0, B1, ca +  64);
                lds128(B2, B3, ca +  80);
                lds128(B4, B5, ca +  96);
                lds128(B6, B7, ca + 112);

                // record PRE-update metrics for step s
                sts64(qa +  0, M0);
                sts64(qa +  8, M1);
                sts64(qa + 16, M2);
                sts64(qa + 24, M3);

                ACS_STEP(A0, A1, A2, A3, A4, A5, A6, A7);

                // prefetch step s+2 (benign <=128B overread into q ring at
                // buffer end — allocated smem, values unused)
                lds128(A0, A1, ca + 128);
                lds128(A2, A3, ca + 144);
                lds128(A4, A5, ca + 160);
                lds128(A6, A7, ca + 176);

                // record PRE-update metrics for step s+1
                sts64(qa + 32, M0);
                sts64(qa + 40, M1);
                sts64(qa + 48, M2);
                sts64(qa + 56, M3);

                ACS_STEP(B0, B1, B2, B3, B4, B5, B6, B7);
            }

            __threadfence_block();
            q_fill[b] = e + 1;
            c_done[b] = e + 1;
        }
    } else if (tid < 32) {
        // idle lanes of warp 0 — exit (participate in NO named barriers)
        return;
    } else if (tid < 96) {
        // ------------------- producers: gmem -> c ring -------------------
        int p = tid - 32;   // 0..63
        const float4* src = reinterpret_cast<const float4*>(g_cneg);
        const long total4 = (long)T_LEN * 4;
        for (int k = 0; k < NCHUNK; k++) {
            int b = k & (NBUF - 1);
            int e = k >> 2;
            if (p == 0) { while (c_done[b] < e) {} }
            asm volatile("bar.sync 1, 64;" ::: "memory");
            float4* dst = reinterpret_cast<float4*>(c_ring + (size_t)b * CH * 8);
            long base4 = (long)k * (CH * 4);
#pragma unroll
            for (int j = 0; j < 16; j++) {
                int i = p + j * 64;                       // CH*4 = 1024 float4 per chunk
                if (base4 + i < total4) dst[i] = src[base4 + i];
            }
            asm volatile("bar.sync 1, 64;" ::: "memory");   // also drains STS
            if (p == 0) c_fill[b] = e + 1;
        }
    } else {
        // ------------------- drainers: q ring -> det/conf -> out ----------
        int d = tid - 96;  // 0..127
        for (int k = 0; k < NCHUNK; k++) {
            int b = k & (NBUF - 1);
            int e = k >> 2;
            if (d == 0) { while (q_fill[b] < e + 1) {} }
            asm volatile("bar.sync 2, 128;" ::: "memory");
            __threadfence_block();
            const ull* qb = q_ring + (size_t)b * CH * 4;
            int n = (k == NCHUNK - 1) ? (T_LEN - k * CH) : CH;
            for (int s = d; s < n; s += 128) {
                ull u0 = qb[4 * s + 0];
                ull u1 = qb[4 * s + 1];
                ull u2 = qb[4 * s + 2];
                ull u3 = qb[4 * s + 3];
                float q[8] = { lof(u0), hif(u0), lof(u1), hif(u1),
                               lof(u2), hif(u2), lof(u3), hif(u3) };
                float m = q[0];
                int idx = 0;
#pragma unroll
                for (int s2 = 1; s2 < 8; s2++)
                    if (q[s2] < m) { m = q[s2]; idx = s2; }  // first-index argmin
                float sum = 0.0f;
#pragma unroll
                for (int s2 = 0; s2 < 8; s2++)
                    sum += expf(-(q[s2] - m));
                int t = k * CH + s;
                out[t]         = (float)(idx & 1);   // detected_word
                out[T_LEN + t] = 1.0f / sum;         // 2 * confidence_word (== 2/sum16)
            }
            asm volatile("bar.sync 2, 128;" ::: "memory");
            if (d == 0) q_done[b] = e + 1;
        }
    }
}

// ---------------------------------------------------------------------------
// Launch. Inputs: rx[1e6], W1[75], b1[75], W2[1200], b2[16].
// Output: 2*T floats, det first then 2*conf.
// ---------------------------------------------------------------------------
extern "C" void kernel_launch(void* const* d_in, const int* in_sizes, int n_in,
                              void* d_out, int out_size)
{
    const float* rx = (const float*)d_in[0];
    const float* W1 = (const float*)d_in[1];
    const float* b1 = (const float*)d_in[2];
    const float* W2 = (const float*)d_in[3];
    const float* b2 = (const float*)d_in[4];
    float* out = (float*)d_out;

    cudaFuncSetAttribute(pipeline_kernel,
                         cudaFuncAttributeMaxDynamicSharedMemorySize, SMEM_BYTES);

    int blocks = (T_LEN + 255) / 256;
    priors_kernel<<<blocks, 256>>>(rx, W1, b1, W2, b2);
    pipeline_kernel<<<1, 224, SMEM_BYTES>>>(out);
}